// round 1
// baseline (speedup 1.0000x reference)
#include <cuda_runtime.h>
#include <math.h>

// Problem constants
#define NT   4096          // B*T tokens
#define DM   1024          // model dim
#define FM   4096          // ffn dim
#define EM   8             // experts
#define NR   8192          // total assignments = NT * TOP_K

// ---------------------------------------------------------------------------
// Scratch (device globals; no runtime allocation allowed)
// ---------------------------------------------------------------------------
__device__ float g_usage[EM];
__device__ int   g_count[EM];
__device__ int   g_offset[EM];
__device__ int   g_cursor[EM];
__device__ int   g_tok_e[NT * 2];
__device__ float g_tok_w[NT * 2];
__device__ int   g_rowToken[NR];
__device__ float g_rowWeight[NR];
__device__ float g_H[(size_t)NR * FM];   // 134 MB intermediate h = silu(gate)*up

// ---------------------------------------------------------------------------
// Kernel 1: zero output + per-launch counters (graph replays need fresh state)
// ---------------------------------------------------------------------------
__global__ void zero_kernel(float* __restrict__ out) {
    int idx = blockIdx.x * blockDim.x + threadIdx.x;
    int stride = gridDim.x * blockDim.x;
    for (int i = idx; i < NT * DM; i += stride) out[i] = 0.0f;
    if (idx < EM) { g_count[idx] = 0; g_usage[idx] = 0.0f; }
}

// ---------------------------------------------------------------------------
// Kernel 2: router. One block per token. logits[8] = x[t,:] . Wr[:,e]
// ---------------------------------------------------------------------------
__global__ __launch_bounds__(256) void router_kernel(const float* __restrict__ x,
                                                     const float* __restrict__ Wr) {
    int t = blockIdx.x;
    int tid = threadIdx.x;

    float acc[EM];
#pragma unroll
    for (int e = 0; e < EM; e++) acc[e] = 0.0f;

    // each thread handles 4 consecutive d values
    const float4 xv = *reinterpret_cast<const float4*>(x + (size_t)t * DM + tid * 4);
    const float xs[4] = {xv.x, xv.y, xv.z, xv.w};
#pragma unroll
    for (int i = 0; i < 4; i++) {
        const float4* wr = reinterpret_cast<const float4*>(Wr + (size_t)(tid * 4 + i) * EM);
        float4 a = wr[0], b = wr[1];
        float xd = xs[i];
        acc[0] += xd * a.x; acc[1] += xd * a.y; acc[2] += xd * a.z; acc[3] += xd * a.w;
        acc[4] += xd * b.x; acc[5] += xd * b.y; acc[6] += xd * b.z; acc[7] += xd * b.w;
    }

    // warp reduce then cross-warp reduce in smem
#pragma unroll
    for (int e = 0; e < EM; e++)
#pragma unroll
        for (int off = 16; off; off >>= 1)
            acc[e] += __shfl_down_sync(0xffffffffu, acc[e], off);

    __shared__ float ws[8][EM];
    int lane = tid & 31, warp = tid >> 5;
    if (lane == 0) {
#pragma unroll
        for (int e = 0; e < EM; e++) ws[warp][e] = acc[e];
    }
    __syncthreads();

    if (tid == 0) {
        float lg[EM];
#pragma unroll
        for (int e = 0; e < EM; e++) {
            float s = 0.0f;
#pragma unroll
            for (int w = 0; w < 8; w++) s += ws[w][e];
            lg[e] = s;
        }
        // full softmax for usage / load-balancing loss
        float m = lg[0];
#pragma unroll
        for (int e = 1; e < EM; e++) m = fmaxf(m, lg[e]);
        float p[EM], s = 0.0f;
#pragma unroll
        for (int e = 0; e < EM; e++) { p[e] = expf(lg[e] - m); s += p[e]; }
        float inv = 1.0f / s;
#pragma unroll
        for (int e = 0; e < EM; e++) atomicAdd(&g_usage[e], p[e] * inv);

        // top-2 (ties -> lower index, matching jax.lax.top_k)
        int i0 = 0;
#pragma unroll
        for (int e = 1; e < EM; e++) if (lg[e] > lg[i0]) i0 = e;
        int i1 = -1;
#pragma unroll
        for (int e = 0; e < EM; e++)
            if (e != i0 && (i1 < 0 || lg[e] > lg[i1])) i1 = e;

        float e1 = expf(lg[i1] - lg[i0]);
        float sw = 1.0f + e1;
        g_tok_e[2 * t + 0] = i0;
        g_tok_e[2 * t + 1] = i1;
        g_tok_w[2 * t + 0] = 1.0f / sw;
        g_tok_w[2 * t + 1] = e1 / sw;
        atomicAdd(&g_count[i0], 1);
        atomicAdd(&g_count[i1], 1);
    }
}

// ---------------------------------------------------------------------------
// Kernel 3: exclusive prefix over counts + load-balancing loss scalar
// ---------------------------------------------------------------------------
__global__ void prefix_kernel(float* __restrict__ out, int out_size) {
    if (threadIdx.x == 0 && blockIdx.x == 0) {
        int off = 0;
#pragma unroll
        for (int e = 0; e < EM; e++) {
            g_offset[e] = off;
            g_cursor[e] = off;
            off += g_count[e];
        }
        float loss = 0.0f;
#pragma unroll
        for (int e = 0; e < EM; e++) {
            float u = g_usage[e] * (1.0f / (float)NT);
            loss += u * u;
        }
        loss *= (float)EM;
        if (out_size > NT * DM) out[NT * DM] = loss;
    }
}

// ---------------------------------------------------------------------------
// Kernel 4: scatter (token, k) assignments into per-expert contiguous rows
// ---------------------------------------------------------------------------
__global__ void scatter_kernel() {
    int t = blockIdx.x * blockDim.x + threadIdx.x;
    if (t >= NT) return;
#pragma unroll
    for (int k = 0; k < 2; k++) {
        int e = g_tok_e[2 * t + k];
        int pos = atomicAdd(&g_cursor[e], 1);
        g_rowToken[pos] = t;
        g_rowWeight[pos] = g_tok_w[2 * t + k];
    }
}

// ---------------------------------------------------------------------------
// Kernel 5: fused gate/up GEMM + SiLU*up -> H
//   per expert: H[r, f] = silu(X W1)[r,f] * (X W3)[r,f]
//   tile: BM=64 (rows), BN=64 (f), BK=16. 256 threads, 4x4 micro-tile, dual acc.
// ---------------------------------------------------------------------------
__global__ __launch_bounds__(256) void ffn1_kernel(const float* __restrict__ x,
                                                   const float* __restrict__ W1,
                                                   const float* __restrict__ W3) {
    int e = blockIdx.z;
    int n_e = g_count[e];
    int m0 = blockIdx.x * 64;
    if (m0 >= n_e) return;
    int f0 = blockIdx.y * 64;
    int rbase = g_offset[e];
    int tid = threadIdx.x;

    __shared__ float As[16][64];
    __shared__ float B1s[16][64];
    __shared__ float B3s[16][64];

    // A loader mapping: 64 rows x 16 k, one float4 per thread
    int arow = tid >> 2;
    int ac = (tid & 3) * 4;
    int gr = m0 + arow;
    int tok = (gr < n_e) ? g_rowToken[rbase + gr] : -1;

    // B loader mapping: 16 k x 64 f, one float4 per thread per matrix
    int bk = tid >> 4;
    int bf = (tid & 15) * 4;
    const float* W1e = W1 + (size_t)e * DM * FM;
    const float* W3e = W3 + (size_t)e * DM * FM;

    int ty = tid >> 4;   // 0..15 -> rows ty*4..+3
    int tx = tid & 15;   // 0..15 -> cols tx*4..+3

    float ag[4][4], au[4][4];
#pragma unroll
    for (int i = 0; i < 4; i++)
#pragma unroll
        for (int j = 0; j < 4; j++) { ag[i][j] = 0.0f; au[i][j] = 0.0f; }

    for (int k0 = 0; k0 < DM; k0 += 16) {
        float4 av = make_float4(0.f, 0.f, 0.f, 0.f);
        if (tok >= 0)
            av = *reinterpret_cast<const float4*>(x + (size_t)tok * DM + k0 + ac);
        As[ac + 0][arow] = av.x;
        As[ac + 1][arow] = av.y;
        As[ac + 2][arow] = av.z;
        As[ac + 3][arow] = av.w;

        *reinterpret_cast<float4*>(&B1s[bk][bf]) =
            *reinterpret_cast<const float4*>(&W1e[(size_t)(k0 + bk) * FM + f0 + bf]);
        *reinterpret_cast<float4*>(&B3s[bk][bf]) =
            *reinterpret_cast<const float4*>(&W3e[(size_t)(k0 + bk) * FM + f0 + bf]);
        __syncthreads();

#pragma unroll
        for (int kk = 0; kk < 16; kk++) {
            float4 a  = *reinterpret_cast<const float4*>(&As[kk][ty * 4]);
            float4 b1 = *reinterpret_cast<const float4*>(&B1s[kk][tx * 4]);
            float4 b3 = *reinterpret_cast<const float4*>(&B3s[kk][tx * 4]);
            float aa[4] = {a.x, a.y, a.z, a.w};
            float bb1[4] = {b1.x, b1.y, b1.z, b1.w};
            float bb3[4] = {b3.x, b3.y, b3.z, b3.w};
#pragma unroll
            for (int i = 0; i < 4; i++)
#pragma unroll
                for (int j = 0; j < 4; j++) {
                    ag[i][j] = fmaf(aa[i], bb1[j], ag[i][j]);
                    au[i][j] = fmaf(aa[i], bb3[j], au[i][j]);
                }
        }
        __syncthreads();
    }

    // epilogue: h = silu(gate) * up
#pragma unroll
    for (int i = 0; i < 4; i++) {
        int r = m0 + ty * 4 + i;
        if (r < n_e) {
            float4 hv;
            float g, u, sig;
            g = ag[i][0]; u = au[i][0]; sig = 1.0f / (1.0f + expf(-g)); hv.x = g * sig * u;
            g = ag[i][1]; u = au[i][1]; sig = 1.0f / (1.0f + expf(-g)); hv.y = g * sig * u;
            g = ag[i][2]; u = au[i][2]; sig = 1.0f / (1.0f + expf(-g)); hv.z = g * sig * u;
            g = ag[i][3]; u = au[i][3]; sig = 1.0f / (1.0f + expf(-g)); hv.w = g * sig * u;
            *reinterpret_cast<float4*>(&g_H[(size_t)(rbase + r) * FM + f0 + tx * 4]) = hv;
        }
    }
}

// ---------------------------------------------------------------------------
// Kernel 6: down GEMM: out[tok, :] += w * (H[r, :] . W2[e])
//   tile: BM=128, BN=64 (d), BK=16. 256 threads, 8x4 micro-tile.
// ---------------------------------------------------------------------------
__global__ __launch_bounds__(256) void ffn2_kernel(const float* __restrict__ W2,
                                                   float* __restrict__ out) {
    int e = blockIdx.z;
    int n_e = g_count[e];
    int m0 = blockIdx.x * 128;
    if (m0 >= n_e) return;
    int n0 = blockIdx.y * 64;
    int rbase = g_offset[e];
    int tid = threadIdx.x;

    __shared__ float As[16][128];
    __shared__ float Bs[16][64];

    int arow = tid >> 2;          // 0..63, second row = +64
    int ac = (tid & 3) * 4;
    bool v0 = (m0 + arow) < n_e;
    bool v1 = (m0 + arow + 64) < n_e;
    const float* h0 = &g_H[(size_t)(rbase + m0 + arow) * FM];
    const float* h1 = &g_H[(size_t)(rbase + m0 + arow + 64) * FM];

    int bk = tid >> 4;
    int bf = (tid & 15) * 4;
    const float* W2e = W2 + (size_t)e * FM * DM;

    int ty = tid >> 4;   // rows ty*8..+7
    int tx = tid & 15;   // cols tx*4..+3

    float acc[8][4];
#pragma unroll
    for (int i = 0; i < 8; i++)
#pragma unroll
        for (int j = 0; j < 4; j++) acc[i][j] = 0.0f;

    for (int k0 = 0; k0 < FM; k0 += 16) {
        float4 a0 = make_float4(0.f, 0.f, 0.f, 0.f);
        float4 a1 = make_float4(0.f, 0.f, 0.f, 0.f);
        if (v0) a0 = *reinterpret_cast<const float4*>(h0 + k0 + ac);
        if (v1) a1 = *reinterpret_cast<const float4*>(h1 + k0 + ac);
        As[ac + 0][arow] = a0.x; As[ac + 1][arow] = a0.y;
        As[ac + 2][arow] = a0.z; As[ac + 3][arow] = a0.w;
        As[ac + 0][arow + 64] = a1.x; As[ac + 1][arow + 64] = a1.y;
        As[ac + 2][arow + 64] = a1.z; As[ac + 3][arow + 64] = a1.w;

        *reinterpret_cast<float4*>(&Bs[bk][bf]) =
            *reinterpret_cast<const float4*>(&W2e[(size_t)(k0 + bk) * DM + n0 + bf]);
        __syncthreads();

#pragma unroll
        for (int kk = 0; kk < 16; kk++) {
            float4 aA = *reinterpret_cast<const float4*>(&As[kk][ty * 8]);
            float4 aB = *reinterpret_cast<const float4*>(&As[kk][ty * 8 + 4]);
            float4 b  = *reinterpret_cast<const float4*>(&Bs[kk][tx * 4]);
            float aa[8] = {aA.x, aA.y, aA.z, aA.w, aB.x, aB.y, aB.z, aB.w};
            float bb[4] = {b.x, b.y, b.z, b.w};
#pragma unroll
            for (int i = 0; i < 8; i++)
#pragma unroll
                for (int j = 0; j < 4; j++)
                    acc[i][j] = fmaf(aa[i], bb[j], acc[i][j]);
        }
        __syncthreads();
    }

#pragma unroll
    for (int i = 0; i < 8; i++) {
        int r = m0 + ty * 8 + i;
        if (r < n_e) {
            int gidx = rbase + r;
            float wgt = g_rowWeight[gidx];
            int tok = g_rowToken[gidx];
            float* o = &out[(size_t)tok * DM + n0 + tx * 4];
            atomicAdd(o + 0, wgt * acc[i][0]);
            atomicAdd(o + 1, wgt * acc[i][1]);
            atomicAdd(o + 2, wgt * acc[i][2]);
            atomicAdd(o + 3, wgt * acc[i][3]);
        }
    }
}

// ---------------------------------------------------------------------------
// Launch
// ---------------------------------------------------------------------------
extern "C" void kernel_launch(void* const* d_in, const int* in_sizes, int n_in,
                              void* d_out, int out_size) {
    const float* x  = (const float*)d_in[0];   // [B,T,D]
    const float* Wr = (const float*)d_in[1];   // [D,E]
    const float* W1 = (const float*)d_in[2];   // [E,D,F]
    const float* W3 = (const float*)d_in[3];   // [E,D,F]
    const float* W2 = (const float*)d_in[4];   // [E,F,D]
    float* out = (float*)d_out;

    zero_kernel<<<4096, 256>>>(out);
    router_kernel<<<NT, 256>>>(x, Wr);
    prefix_kernel<<<1, 32>>>(out, out_size);
    scatter_kernel<<<16, 256>>>();
    ffn1_kernel<<<dim3(64, FM / 64, EM), 256>>>(x, W1, W3);
    ffn2_kernel<<<dim3(32, DM / 64, EM), 256>>>(W2, out);
}

// round 4
// speedup vs baseline: 2.4042x; 2.4042x over previous
#include <cuda_runtime.h>
#include <cstdint>
#include <math.h>

// Problem constants
#define NT   4096          // B*T tokens
#define DM   1024          // model dim
#define FM   4096          // ffn dim
#define EM   8             // experts
#define NR   8192          // total assignments = NT * TOP_K

// ---------------------------------------------------------------------------
// Scratch (device globals; no runtime allocation allowed)
// ---------------------------------------------------------------------------
__device__ float g_usage[EM];
__device__ int   g_count[EM];
__device__ int   g_offset[EM];
__device__ int   g_cursor[EM];
__device__ int   g_tok_e[NT * 2];
__device__ float g_tok_w[NT * 2];
__device__ int   g_rowToken[NR];
__device__ float g_rowWeight[NR];
__device__ float g_H[(size_t)NR * FM];           // tf32-rounded h = silu(gate)*up
__device__ float g_Xr[(size_t)NT * DM];          // tf32-rounded x
__device__ float g_W1t[(size_t)EM * FM * DM];    // [E][F][D] transposed, rounded
__device__ float g_W3t[(size_t)EM * FM * DM];
__device__ float g_W2t[(size_t)EM * DM * FM];    // [E][D][F] transposed, rounded

// ---------------------------------------------------------------------------
// Helpers (all non-'a' PTX: works on plain sm_103 target)
// ---------------------------------------------------------------------------
__device__ __forceinline__ uint32_t smem_u32(const void* p) {
    uint32_t a;
    asm("{ .reg .u64 t; cvta.to.shared.u64 t, %1; cvt.u32.u64 %0, t; }" : "=r"(a) : "l"(p));
    return a;
}
__device__ __forceinline__ float rna_tf32(float x) {
    float y;
    asm("cvt.rna.tf32.f32 %0, %1;" : "=f"(y) : "f"(x));
    return y;
}
__device__ __forceinline__ uint32_t lds32(uint32_t a) {
    uint32_t v;
    asm("ld.shared.b32 %0, [%1];" : "=r"(v) : "r"(a));
    return v;
}

#define CP16(dst, src) \
    asm volatile("cp.async.cg.shared.global [%0], [%1], 16;" :: "r"(dst), "l"(src))
#define CP16Z(dst, src, sz) \
    asm volatile("cp.async.cg.shared.global [%0], [%1], 16, %2;" :: "r"(dst), "l"(src), "r"(sz))
#define CP_COMMIT() asm volatile("cp.async.commit_group;")
#define CP_WAIT(n)  asm volatile("cp.async.wait_group %0;" :: "n"(n))

// tf32 m16n8k8 mma: C += A*B, accumulators in-place
#define MMA_TF32(C, A, B) \
    asm volatile("mma.sync.aligned.m16n8k8.row.col.f32.tf32.tf32.f32 " \
        "{%0,%1,%2,%3},{%4,%5,%6,%7},{%8,%9},{%0,%1,%2,%3};" \
        : "+f"((C)[0]), "+f"((C)[1]), "+f"((C)[2]), "+f"((C)[3]) \
        : "r"((A)[0]), "r"((A)[1]), "r"((A)[2]), "r"((A)[3]), \
          "r"((B)[0]), "r"((B)[1]))

// ---------------------------------------------------------------------------
// Kernel 1: zero output + counters
// ---------------------------------------------------------------------------
__global__ void zero_kernel(float* __restrict__ out) {
    int idx = blockIdx.x * blockDim.x + threadIdx.x;
    int stride = gridDim.x * blockDim.x;
    for (int i = idx; i < NT * DM; i += stride) out[i] = 0.0f;
    if (idx < EM) { g_count[idx] = 0; g_usage[idx] = 0.0f; }
}

// ---------------------------------------------------------------------------
// Kernel 2: router
// ---------------------------------------------------------------------------
__global__ __launch_bounds__(256) void router_kernel(const float* __restrict__ x,
                                                     const float* __restrict__ Wr) {
    int t = blockIdx.x;
    int tid = threadIdx.x;
    float acc[EM];
#pragma unroll
    for (int e = 0; e < EM; e++) acc[e] = 0.0f;
    const float4 xv = *reinterpret_cast<const float4*>(x + (size_t)t * DM + tid * 4);
    const float xs[4] = {xv.x, xv.y, xv.z, xv.w};
#pragma unroll
    for (int i = 0; i < 4; i++) {
        const float4* wr = reinterpret_cast<const float4*>(Wr + (size_t)(tid * 4 + i) * EM);
        float4 a = wr[0], b = wr[1];
        float xd = xs[i];
        acc[0] += xd * a.x; acc[1] += xd * a.y; acc[2] += xd * a.z; acc[3] += xd * a.w;
        acc[4] += xd * b.x; acc[5] += xd * b.y; acc[6] += xd * b.z; acc[7] += xd * b.w;
    }
#pragma unroll
    for (int e = 0; e < EM; e++)
#pragma unroll
        for (int off = 16; off; off >>= 1)
            acc[e] += __shfl_down_sync(0xffffffffu, acc[e], off);
    __shared__ float ws[8][EM];
    int lane = tid & 31, warp = tid >> 5;
    if (lane == 0) {
#pragma unroll
        for (int e = 0; e < EM; e++) ws[warp][e] = acc[e];
    }
    __syncthreads();
    if (tid == 0) {
        float lg[EM];
#pragma unroll
        for (int e = 0; e < EM; e++) {
            float s = 0.0f;
#pragma unroll
            for (int w = 0; w < 8; w++) s += ws[w][e];
            lg[e] = s;
        }
        float m = lg[0];
#pragma unroll
        for (int e = 1; e < EM; e++) m = fmaxf(m, lg[e]);
        float p[EM], s = 0.0f;
#pragma unroll
        for (int e = 0; e < EM; e++) { p[e] = expf(lg[e] - m); s += p[e]; }
        float inv = 1.0f / s;
#pragma unroll
        for (int e = 0; e < EM; e++) atomicAdd(&g_usage[e], p[e] * inv);
        int i0 = 0;
#pragma unroll
        for (int e = 1; e < EM; e++) if (lg[e] > lg[i0]) i0 = e;
        int i1 = -1;
#pragma unroll
        for (int e = 0; e < EM; e++)
            if (e != i0 && (i1 < 0 || lg[e] > lg[i1])) i1 = e;
        float e1 = expf(lg[i1] - lg[i0]);
        float sw = 1.0f + e1;
        g_tok_e[2 * t + 0] = i0;
        g_tok_e[2 * t + 1] = i1;
        g_tok_w[2 * t + 0] = 1.0f / sw;
        g_tok_w[2 * t + 1] = e1 / sw;
        atomicAdd(&g_count[i0], 1);
        atomicAdd(&g_count[i1], 1);
    }
}

// ---------------------------------------------------------------------------
// Kernel 3: prefix + loss
// ---------------------------------------------------------------------------
__global__ void prefix_kernel(float* __restrict__ out, int out_size) {
    if (threadIdx.x == 0 && blockIdx.x == 0) {
        int off = 0;
#pragma unroll
        for (int e = 0; e < EM; e++) {
            g_offset[e] = off;
            g_cursor[e] = off;
            off += g_count[e];
        }
        float loss = 0.0f;
#pragma unroll
        for (int e = 0; e < EM; e++) {
            float u = g_usage[e] * (1.0f / (float)NT);
            loss += u * u;
        }
        loss *= (float)EM;
        if (out_size > NT * DM) out[NT * DM] = loss;
    }
}

// ---------------------------------------------------------------------------
// Kernel 4: scatter
// ---------------------------------------------------------------------------
__global__ void scatter_kernel() {
    int t = blockIdx.x * blockDim.x + threadIdx.x;
    if (t >= NT) return;
#pragma unroll
    for (int k = 0; k < 2; k++) {
        int e = g_tok_e[2 * t + k];
        int pos = atomicAdd(&g_cursor[e], 1);
        g_rowToken[pos] = t;
        g_rowWeight[pos] = g_tok_w[2 * t + k];
    }
}

// ---------------------------------------------------------------------------
// Kernel T: transpose + tf32-round one [R,C] plane per expert -> dst[c][r]
// ---------------------------------------------------------------------------
__global__ __launch_bounds__(256) void transpose_round(const float* __restrict__ src,
                                                       float* __restrict__ dst,
                                                       int R, int C) {
    __shared__ float tile[32][33];
    size_t plane = (size_t)blockIdx.z * R * C;
    src += plane; dst += plane;
    int c0 = blockIdx.x * 32, r0 = blockIdx.y * 32;
    int tx = threadIdx.x & 31, ty = threadIdx.x >> 5;
#pragma unroll
    for (int i = 0; i < 4; i++)
        tile[ty + i * 8][tx] = src[(size_t)(r0 + ty + i * 8) * C + c0 + tx];
    __syncthreads();
#pragma unroll
    for (int i = 0; i < 4; i++)
        dst[(size_t)(c0 + ty + i * 8) * R + r0 + tx] = rna_tf32(tile[tx][ty + i * 8]);
}

// ---------------------------------------------------------------------------
// Kernel R: round x -> g_Xr
// ---------------------------------------------------------------------------
__global__ void round_x_kernel(const float* __restrict__ x) {
    int i = blockIdx.x * blockDim.x + threadIdx.x;
    float4 v = reinterpret_cast<const float4*>(x)[i];
    v.x = rna_tf32(v.x); v.y = rna_tf32(v.y);
    v.z = rna_tf32(v.z); v.w = rna_tf32(v.w);
    reinterpret_cast<float4*>(g_Xr)[i] = v;
}

// ---------------------------------------------------------------------------
// Kernel 5: ffn1 via tf32 mma.sync. BM=128 x BN=64 (gate AND up), BK=32.
// smem stage: A 16KB | B1 8KB | B3 8KB = 32KB, double buffered.
// 8 warps in 4(m) x 2(n); warp tile 32x32 per matrix.
// NOTE: x is read from g_Xr (device symbol referenced IN DEVICE CODE —
// passing it as a host-side kernel arg was the Round-3 bug).
// ---------------------------------------------------------------------------
#define F1_STAGE 32768
#define F1_SMEM  (2 * F1_STAGE)

__global__ __launch_bounds__(256) void ffn1_mma() {
    int e = blockIdx.z;
    int n_e = g_count[e];
    int m0 = blockIdx.x * 128;
    if (m0 >= n_e) return;
    int f0 = blockIdx.y * 64;
    int rbase = g_offset[e];
    extern __shared__ char smem[];
    uint32_t sbase = smem_u32(smem);
    int tid = threadIdx.x, wid = tid >> 5, lane = tid & 31;
    int g = lane >> 2, tig = lane & 3;
    int wm = (wid >> 1) * 32, wn = (wid & 1) * 32;

    // loader mapping: chunk index = (row, c16); row = tid>>3 (+32*i), c16 = tid&7
    int lrow = tid >> 3;
    int c16 = tid & 7;
    const float* asrc[4];
    uint32_t asz[4], adst[4];
#pragma unroll
    for (int i = 0; i < 4; i++) {
        int row = lrow + 32 * i;
        int grow = m0 + row;
        int tok = (grow < n_e) ? g_rowToken[rbase + grow] : 0;
        asrc[i] = g_Xr + (size_t)tok * DM + c16 * 4;
        asz[i] = (grow < n_e) ? 16u : 0u;
        adst[i] = (uint32_t)(row * 128 + ((c16 ^ (row & 7)) * 16));
    }
    const float* b1src[2];
    const float* b3src[2];
    uint32_t bdst[2];
#pragma unroll
    for (int i = 0; i < 2; i++) {
        int row = lrow + 32 * i;
        b1src[i] = g_W1t + ((size_t)e * FM + f0 + row) * DM + c16 * 4;
        b3src[i] = g_W3t + ((size_t)e * FM + f0 + row) * DM + c16 * 4;
        bdst[i] = (uint32_t)(row * 128 + ((c16 ^ (row & 7)) * 16));
    }

    float ag[2][4][4], au[2][4][4];
#pragma unroll
    for (int mi = 0; mi < 2; mi++)
#pragma unroll
        for (int ni = 0; ni < 4; ni++)
#pragma unroll
            for (int j = 0; j < 4; j++) { ag[mi][ni][j] = 0.0f; au[mi][ni][j] = 0.0f; }

#define F1_FILL(s, k0) do {                                              \
        uint32_t ab_ = sbase + (s) * F1_STAGE;                           \
        uint32_t b1_ = ab_ + 16384, b3_ = ab_ + 24576;                   \
        _Pragma("unroll")                                                \
        for (int i_ = 0; i_ < 4; i_++) CP16Z(ab_ + adst[i_], asrc[i_] + (k0), asz[i_]); \
        _Pragma("unroll")                                                \
        for (int i_ = 0; i_ < 2; i_++) {                                 \
            CP16(b1_ + bdst[i_], b1src[i_] + (k0));                      \
            CP16(b3_ + bdst[i_], b3src[i_] + (k0));                      \
        } } while (0)

    F1_FILL(0, 0);
    CP_COMMIT();
    const int NKC = DM / 32;
    for (int c = 0; c < NKC; c++) {
        int p = c & 1;
        if (c + 1 < NKC) {
            F1_FILL(p ^ 1, (c + 1) * 32);
            CP_COMMIT();
            CP_WAIT(1);
        } else {
            CP_WAIT(0);
        }
        __syncthreads();
        uint32_t ab = sbase + p * F1_STAGE;
        uint32_t b1b = ab + 16384, b3b = ab + 24576;
#pragma unroll
        for (int k8 = 0; k8 < 4; k8++) {
            uint32_t sw0 = (uint32_t)((((2 * k8) ^ g) * 16) + tig * 4);
            uint32_t sw1 = (uint32_t)((((2 * k8 + 1) ^ g) * 16) + tig * 4);
            uint32_t a[2][4];
#pragma unroll
            for (int mi = 0; mi < 2; mi++) {
                uint32_t r0 = ab + (wm + mi * 16 + g) * 128;
                uint32_t r1 = r0 + 8 * 128;
                a[mi][0] = lds32(r0 + sw0);
                a[mi][1] = lds32(r1 + sw0);
                a[mi][2] = lds32(r0 + sw1);
                a[mi][3] = lds32(r1 + sw1);
            }
            uint32_t b1[4][2], b3[4][2];
#pragma unroll
            for (int ni = 0; ni < 4; ni++) {
                uint32_t nr = (uint32_t)((wn + ni * 8 + g) * 128);
                b1[ni][0] = lds32(b1b + nr + sw0);
                b1[ni][1] = lds32(b1b + nr + sw1);
                b3[ni][0] = lds32(b3b + nr + sw0);
                b3[ni][1] = lds32(b3b + nr + sw1);
            }
#pragma unroll
            for (int mi = 0; mi < 2; mi++)
#pragma unroll
                for (int ni = 0; ni < 4; ni++) {
                    MMA_TF32(ag[mi][ni], a[mi], b1[ni]);
                    MMA_TF32(au[mi][ni], a[mi], b3[ni]);
                }
        }
        __syncthreads();
    }

    // epilogue: h = silu(gate)*up, rounded, to g_H
#pragma unroll
    for (int mi = 0; mi < 2; mi++)
#pragma unroll
        for (int half = 0; half < 2; half++) {
            int row = m0 + wm + mi * 16 + g + half * 8;
            if (row < n_e) {
                float* hr = g_H + (size_t)(rbase + row) * FM + f0 + wn;
#pragma unroll
                for (int ni = 0; ni < 4; ni++) {
                    float gv0 = ag[mi][ni][half * 2 + 0];
                    float gv1 = ag[mi][ni][half * 2 + 1];
                    float uv0 = au[mi][ni][half * 2 + 0];
                    float uv1 = au[mi][ni][half * 2 + 1];
                    float h0 = rna_tf32(gv0 * uv0 / (1.0f + __expf(-gv0)));
                    float h1 = rna_tf32(gv1 * uv1 / (1.0f + __expf(-gv1)));
                    *reinterpret_cast<float2*>(hr + ni * 8 + 2 * tig) = make_float2(h0, h1);
                }
            }
        }
#undef F1_FILL
}

// ---------------------------------------------------------------------------
// Kernel 6: ffn2 via tf32 mma.sync. BM=128 x BN=64, BK=32, K=FM.
// smem stage: A 16KB | B 8KB = 24KB, double buffered.
// ---------------------------------------------------------------------------
#define F2_STAGE 24576
#define F2_SMEM  (2 * F2_STAGE)

__global__ __launch_bounds__(256) void ffn2_mma(float* __restrict__ out) {
    int e = blockIdx.z;
    int n_e = g_count[e];
    int m0 = blockIdx.x * 128;
    if (m0 >= n_e) return;
    int n0 = blockIdx.y * 64;
    int rbase = g_offset[e];
    extern __shared__ char smem[];
    uint32_t sbase = smem_u32(smem);
    int tid = threadIdx.x, wid = tid >> 5, lane = tid & 31;
    int g = lane >> 2, tig = lane & 3;
    int wm = (wid >> 1) * 32, wn = (wid & 1) * 32;

    int lrow = tid >> 3;
    int c16 = tid & 7;
    const float* asrc[4];
    uint32_t asz[4], adst[4];
#pragma unroll
    for (int i = 0; i < 4; i++) {
        int row = lrow + 32 * i;
        int grow = m0 + row;
        asrc[i] = g_H + (size_t)(rbase + ((grow < n_e) ? grow : 0)) * FM + c16 * 4;
        asz[i] = (grow < n_e) ? 16u : 0u;
        adst[i] = (uint32_t)(row * 128 + ((c16 ^ (row & 7)) * 16));
    }
    const float* bsrc[2];
    uint32_t bdst[2];
#pragma unroll
    for (int i = 0; i < 2; i++) {
        int row = lrow + 32 * i;
        bsrc[i] = g_W2t + ((size_t)e * DM + n0 + row) * FM + c16 * 4;
        bdst[i] = (uint32_t)(row * 128 + ((c16 ^ (row & 7)) * 16));
    }

    float acc[2][4][4];
#pragma unroll
    for (int mi = 0; mi < 2; mi++)
#pragma unroll
        for (int ni = 0; ni < 4; ni++)
#pragma unroll
            for (int j = 0; j < 4; j++) acc[mi][ni][j] = 0.0f;

#define F2_FILL(s, k0) do {                                              \
        uint32_t ab_ = sbase + (s) * F2_STAGE;                           \
        uint32_t bb_ = ab_ + 16384;                                      \
        _Pragma("unroll")                                                \
        for (int i_ = 0; i_ < 4; i_++) CP16Z(ab_ + adst[i_], asrc[i_] + (k0), asz[i_]); \
        _Pragma("unroll")                                                \
        for (int i_ = 0; i_ < 2; i_++) CP16(bb_ + bdst[i_], bsrc[i_] + (k0)); \
    } while (0)

    F2_FILL(0, 0);
    CP_COMMIT();
    const int NKC = FM / 32;
    for (int c = 0; c < NKC; c++) {
        int p = c & 1;
        if (c + 1 < NKC) {
            F2_FILL(p ^ 1, (c + 1) * 32);
            CP_COMMIT();
            CP_WAIT(1);
        } else {
            CP_WAIT(0);
        }
        __syncthreads();
        uint32_t ab = sbase + p * F2_STAGE;
        uint32_t bb = ab + 16384;
#pragma unroll
        for (int k8 = 0; k8 < 4; k8++) {
            uint32_t sw0 = (uint32_t)((((2 * k8) ^ g) * 16) + tig * 4);
            uint32_t sw1 = (uint32_t)((((2 * k8 + 1) ^ g) * 16) + tig * 4);
            uint32_t a[2][4];
#pragma unroll
            for (int mi = 0; mi < 2; mi++) {
                uint32_t r0 = ab + (wm + mi * 16 + g) * 128;
                uint32_t r1 = r0 + 8 * 128;
                a[mi][0] = lds32(r0 + sw0);
                a[mi][1] = lds32(r1 + sw0);
                a[mi][2] = lds32(r0 + sw1);
                a[mi][3] = lds32(r1 + sw1);
            }
            uint32_t b[4][2];
#pragma unroll
            for (int ni = 0; ni < 4; ni++) {
                uint32_t nr = (uint32_t)((wn + ni * 8 + g) * 128);
                b[ni][0] = lds32(bb + nr + sw0);
                b[ni][1] = lds32(bb + nr + sw1);
            }
#pragma unroll
            for (int mi = 0; mi < 2; mi++)
#pragma unroll
                for (int ni = 0; ni < 4; ni++)
                    MMA_TF32(acc[mi][ni], a[mi], b[ni]);
        }
        __syncthreads();
    }

    // epilogue: weighted atomicAdd into out[token]
#pragma unroll
    for (int mi = 0; mi < 2; mi++)
#pragma unroll
        for (int half = 0; half < 2; half++) {
            int row = m0 + wm + mi * 16 + g + half * 8;
            if (row < n_e) {
                int gi = rbase + row;
                float wgt = g_rowWeight[gi];
                int tok = g_rowToken[gi];
                float* orow = out + (size_t)tok * DM + n0 + wn;
#pragma unroll
                for (int ni = 0; ni < 4; ni++) {
                    atomicAdd(orow + ni * 8 + 2 * tig, wgt * acc[mi][ni][half * 2 + 0]);
                    atomicAdd(orow + ni * 8 + 2 * tig + 1, wgt * acc[mi][ni][half * 2 + 1]);
                }
            }
        }
#undef F2_FILL
}

// ---------------------------------------------------------------------------
// Launch
// ---------------------------------------------------------------------------
extern "C" void kernel_launch(void* const* d_in, const int* in_sizes, int n_in,
                              void* d_out, int out_size) {
    const float* x  = (const float*)d_in[0];   // [B,T,D]
    const float* Wr = (const float*)d_in[1];   // [D,E]
    const float* W1 = (const float*)d_in[2];   // [E,D,F]
    const float* W3 = (const float*)d_in[3];   // [E,D,F]
    const float* W2 = (const float*)d_in[4];   // [E,F,D]
    float* out = (float*)d_out;

    float* w1t; cudaGetSymbolAddress((void**)&w1t, g_W1t);
    float* w3t; cudaGetSymbolAddress((void**)&w3t, g_W3t);
    float* w2t; cudaGetSymbolAddress((void**)&w2t, g_W2t);

    cudaFuncSetAttribute(ffn1_mma, cudaFuncAttributeMaxDynamicSharedMemorySize, F1_SMEM);
    cudaFuncSetAttribute(ffn2_mma, cudaFuncAttributeMaxDynamicSharedMemorySize, F2_SMEM);

    zero_kernel<<<4096, 256>>>(out);
    router_kernel<<<NT, 256>>>(x, Wr);
    prefix_kernel<<<1, 32>>>(out, out_size);
    scatter_kernel<<<16, 256>>>();
    round_x_kernel<<<NT * DM / 4 / 256, 256>>>(x);

    // W1/W3: [E][D][F] -> [E][F][D]; W2: [E][F][D] -> [E][D][F]
    transpose_round<<<dim3(FM / 32, DM / 32, EM), 256>>>(W1, w1t, DM, FM);
    transpose_round<<<dim3(FM / 32, DM / 32, EM), 256>>>(W3, w3t, DM, FM);
    transpose_round<<<dim3(DM / 32, FM / 32, EM), 256>>>(W2, w2t, FM, DM);

    ffn1_mma<<<dim3(32, FM / 64, EM), 256, F1_SMEM>>>();
    ffn2_mma<<<dim3(32, DM / 64, EM), 256, F2_SMEM>>>(out);
}